// round 4
// baseline (speedup 1.0000x reference)
#include <cuda_runtime.h>
#include <math.h>
#include <stdint.h>

// ---------------- problem constants ----------------
#define B_      8
#define H_      128
#define W_      128
#define DIM_    256
#define HEADS_  16
#define DH_     16
#define HW_     (H_*W_)            // 16384
#define M_TOTAL (B_*HW_)           // 131072
#define N_QKV   (3*DIM_)           // 768
#define SLICES  8

// ---------------- scratch (no allocs -> __device__ globals) ----------------
__device__ float g_qkv  [(size_t)M_TOTAL * N_QKV];
__device__ float g_qkv2 [(size_t)M_TOTAL * N_QKV];
__device__ float g_part [SLICES * B_ * HEADS_ * DH_ * DH_];
__device__ float g_attn [B_ * HEADS_ * DH_ * DH_];
__device__ float g_wfT  [B_ * DIM_ * DIM_];
__device__ float g_wqkvT[N_QKV * DIM_];

// ---------------- helpers ----------------
__device__ __forceinline__ uint32_t smem_u32(const void* p) {
    uint32_t a;
    asm("{ .reg .u64 t; cvta.to.shared.u64 t, %1; cvt.u32.u64 %0, t; }" : "=r"(a) : "l"(p));
    return a;
}
__device__ __forceinline__ uint32_t f2tf32(float f) {
    uint32_t r; asm("cvt.rna.tf32.f32 %0, %1;" : "=r"(r) : "f"(f)); return r;
}
__device__ __forceinline__ void cp16(uint32_t daddr, const void* g) {
    asm volatile("cp.async.ca.shared.global [%0], [%1], 16;" :: "r"(daddr), "l"(g));
}
#define CP_COMMIT() asm volatile("cp.async.commit_group;" ::: "memory")
#define CP_WAIT(n)  asm volatile("cp.async.wait_group %0;" :: "n"(n) : "memory")

__device__ __forceinline__ void mma_tf32(float* c, const uint32_t* a, const uint32_t* b) {
    asm volatile(
        "mma.sync.aligned.m16n8k8.row.col.f32.tf32.tf32.f32 "
        "{%0,%1,%2,%3}, {%4,%5,%6,%7}, {%8,%9}, {%0,%1,%2,%3};"
        : "+f"(c[0]), "+f"(c[1]), "+f"(c[2]), "+f"(c[3])
        : "r"(a[0]), "r"(a[1]), "r"(a[2]), "r"(a[3]), "r"(b[0]), "r"(b[1]));
}

// ---------------- tf32 mma.sync GEMM with cp.async double buffering ----------------
// C[M,N] = A[M,K] @ Bt[N,K]^T. CTA 128x128, k-tile 32, 8 warps (2m x 4n), warp 64x32.
#define TM_BM 128
#define TM_BN 128
#define TM_BK 32
#define TM_PAD 36
#define TM_STAGE (2 * TM_BM * TM_PAD)            // floats per stage (A + B)
#define TM_SMEM  (2 * TM_STAGE * 4)              // bytes, 2 stages = 73728

__global__ __launch_bounds__(256, 2) void mgemm_k(
    const float* __restrict__ A, int lda,
    const float* __restrict__ Bt, int ldb, long long b_stride,
    float* __restrict__ C, int ldc,
    int rows_per_batch, int K)
{
    extern __shared__ float smf[];

    const int tid  = threadIdx.x;
    const int lane = tid & 31;
    const int wid  = tid >> 5;
    const int wm   = wid & 1;
    const int wn   = wid >> 1;
    const int gid  = lane >> 2;
    const int tig  = lane & 3;

    const int m0 = blockIdx.y * TM_BM;
    const int n0 = blockIdx.x * TM_BN;
    const int batch = m0 / rows_per_batch;
    const float* Ap = A  + (size_t)m0 * lda;
    const float* Bp = Bt + (size_t)batch * b_stride + (size_t)n0 * ldb;

    float acc[4][4][4];
    #pragma unroll
    for (int mt = 0; mt < 4; mt++)
        #pragma unroll
        for (int nt = 0; nt < 4; nt++)
            #pragma unroll
            for (int r = 0; r < 4; r++) acc[mt][nt][r] = 0.f;

    const int nk = K / TM_BK;

    // stage loader: 8 A-float4 + 8 B-float4 per thread via cp.async
    #define STAGE_LOAD(S, BUF) do {                                              \
        const float* gA = Ap + (S) * TM_BK;                                       \
        const float* gB = Bp + (S) * TM_BK;                                       \
        float* sa = smf + (BUF) * TM_STAGE;                                       \
        float* sb = sa + TM_BM * TM_PAD;                                          \
        _Pragma("unroll")                                                         \
        for (int i = 0; i < 4; i++) {                                             \
            int idx = i * 256 + tid;                                              \
            int r = idx >> 3, c4 = idx & 7;                                       \
            cp16(smem_u32(sa + r * TM_PAD + c4 * 4), gA + (size_t)r * lda + c4 * 4); \
        }                                                                         \
        _Pragma("unroll")                                                         \
        for (int i = 0; i < 4; i++) {                                             \
            int idx = i * 256 + tid;                                              \
            int r = idx >> 3, c4 = idx & 7;                                       \
            cp16(smem_u32(sb + r * TM_PAD + c4 * 4), gB + (size_t)r * ldb + c4 * 4); \
        }                                                                         \
        CP_COMMIT();                                                              \
    } while (0)

    STAGE_LOAD(0, 0);

    for (int s = 0; s < nk; s++) {
        const int buf = s & 1;
        if (s + 1 < nk) { STAGE_LOAD(s + 1, buf ^ 1); CP_WAIT(1); }
        else            { CP_WAIT(0); }
        __syncthreads();

        const float* Asf = smf + buf * TM_STAGE;
        const float* Bsf = Asf + TM_BM * TM_PAD;

        #pragma unroll
        for (int ks = 0; ks < TM_BK / 8; ks++) {
            const int kc = ks * 8 + tig;
            uint32_t af[4][4], bf[4][2];
            #pragma unroll
            for (int mt = 0; mt < 4; mt++) {
                int row = wm * 64 + mt * 16 + gid;
                af[mt][0] = f2tf32(Asf[row * TM_PAD + kc]);
                af[mt][1] = f2tf32(Asf[(row + 8) * TM_PAD + kc]);
                af[mt][2] = f2tf32(Asf[row * TM_PAD + kc + 4]);
                af[mt][3] = f2tf32(Asf[(row + 8) * TM_PAD + kc + 4]);
            }
            #pragma unroll
            for (int nt = 0; nt < 4; nt++) {
                int nrow = wn * 32 + nt * 8 + gid;
                bf[nt][0] = f2tf32(Bsf[nrow * TM_PAD + kc]);
                bf[nt][1] = f2tf32(Bsf[nrow * TM_PAD + kc + 4]);
            }
            #pragma unroll
            for (int mt = 0; mt < 4; mt++)
                #pragma unroll
                for (int nt = 0; nt < 4; nt++)
                    mma_tf32(acc[mt][nt], af[mt], bf[nt]);
        }
        __syncthreads();
    }

    #pragma unroll
    for (int mt = 0; mt < 4; mt++) {
        #pragma unroll
        for (int nt = 0; nt < 4; nt++) {
            int row = m0 + wm * 64 + mt * 16 + gid;
            int col = n0 + wn * 32 + nt * 8 + tig * 2;
            *(float2*)(C + (size_t)row * ldc + col) =
                make_float2(acc[mt][nt][0], acc[mt][nt][1]);
            *(float2*)(C + (size_t)(row + 8) * ldc + col) =
                make_float2(acc[mt][nt][2], acc[mt][nt][3]);
        }
    }
}

// ---------------- small transpose: w_qkv [K=256, N=768] -> [N][K] ----------------
__global__ void transp_k(const float* __restrict__ w, float* __restrict__ wT) {
    int idx = blockIdx.x * blockDim.x + threadIdx.x;
    if (idx >= N_QKV * DIM_) return;
    int n = idx / DIM_, k = idx % DIM_;
    wT[idx] = w[(size_t)k * N_QKV + n];
}

// ---------------- depthwise 3x3 conv, SAME, NHWC, smem-tiled ----------------
// block: 8x32 pixel tile x 16 channels (one c-group). grid: (4, 16, B_*48)
__global__ __launch_bounds__(256) void dwconv_k(const float* __restrict__ in,
                                                const float* __restrict__ w,
                                                float* __restrict__ out)
{
    __shared__ float sm[10][34][16];   // 21760 B

    const int bx = blockIdx.x;             // 0..3
    const int by = blockIdx.y;             // 0..15
    const int bz = blockIdx.z;             // b*48 + g
    const int b  = bz / 48, g48 = bz % 48;
    const int cbase = g48 * 16;             // float offset in [0,768)

    const int tid = threadIdx.x;

    // load 10x34 halo tile, 4 float4 per pixel
    for (int i = tid; i < 10 * 34 * 4; i += 256) {
        int c4 = i & 3;
        int x  = (i >> 2) % 34;
        int y  = (i >> 2) / 34;
        int gy = by * 8 - 1 + y, gx = bx * 32 - 1 + x;
        float4 v = make_float4(0.f, 0.f, 0.f, 0.f);
        if ((unsigned)gy < (unsigned)H_ && (unsigned)gx < (unsigned)W_)
            v = *(const float4*)(in + ((size_t)(b * H_ + gy) * W_ + gx) * N_QKV + cbase + c4 * 4);
        *(float4*)&sm[y][x][c4 * 4] = v;
    }

    const int c4s = tid & 3;
    const int xo  = (tid >> 2) & 31;
    const int yo0 = tid >> 7;               // 0..1
    float4 wv[9];
    #pragma unroll
    for (int t = 0; t < 9; t++)
        wv[t] = *(const float4*)(w + (size_t)t * N_QKV + cbase + c4s * 4);
    __syncthreads();

    #pragma unroll
    for (int i = 0; i < 4; i++) {
        int yo = yo0 + i * 2;
        float4 acc = make_float4(0.f, 0.f, 0.f, 0.f);
        #pragma unroll
        for (int dy = 0; dy < 3; dy++)
            #pragma unroll
            for (int dx = 0; dx < 3; dx++) {
                float4 iv = *(const float4*)&sm[yo + dy][xo + dx][c4s * 4];
                float4 ww = wv[dy * 3 + dx];
                acc.x += iv.x * ww.x; acc.y += iv.y * ww.y;
                acc.z += iv.z * ww.z; acc.w += iv.w * ww.w;
            }
        int gy = by * 8 + yo, gx = bx * 32 + xo;
        *(float4*)(out + ((size_t)(b * H_ + gy) * W_ + gx) * N_QKV + cbase + c4s * 4) = acc;
    }
}

// ---------------- attention partials: 4x4 register tiles ----------------
// 256 threads = 16 (i,j)-tiles x 16 s-groups per block; blocks = (b*h, slice)
__global__ __launch_bounds__(256) void attn_part_k(
    const float* __restrict__ qkv2,
    const float* __restrict__ mean_q, const float* __restrict__ var_q,
    const float* __restrict__ mean_k, const float* __restrict__ var_k,
    float* __restrict__ part)
{
    const int bh = blockIdx.x;
    const int sl = blockIdx.y;
    const int b = bh >> 4, h = bh & 15;
    __shared__ float qs[64][16];
    __shared__ float ks[64][16];
    __shared__ float red[16][16][16];   // [group][i][j]

    const int tid  = threadIdx.x;
    const int tile = tid & 15;
    const int g    = tid >> 4;          // s-group 0..15
    const int it   = tile >> 2, jt = tile & 3;
    const int ls   = tid >> 2;          // load row 0..63
    const int li   = (tid & 3) * 4;
    const float* base = qkv2 + (size_t)b * HW_ * N_QKV + h * DH_;

    float acc[4][4];
    #pragma unroll
    for (int a = 0; a < 4; a++)
        #pragma unroll
        for (int c = 0; c < 4; c++) acc[a][c] = 0.f;

    const int s_beg = sl * (HW_ / SLICES), s_end = s_beg + HW_ / SLICES;

    for (int s0 = s_beg; s0 < s_end; s0 += 64) {
        int s = s0 + ls;
        float mq = mean_q[s], rvq = rsqrtf(var_q[s]);
        float mk = mean_k[s], rvk = rsqrtf(var_k[s]);
        const float* p = base + (size_t)s * N_QKV + li;
        float4 qv = *(const float4*)(p);
        float4 kv = *(const float4*)(p + DIM_);
        qs[ls][li+0] = (qv.x - mq) * rvq;
        qs[ls][li+1] = (qv.y - mq) * rvq;
        qs[ls][li+2] = (qv.z - mq) * rvq;
        qs[ls][li+3] = (qv.w - mq) * rvq;
        ks[ls][li+0] = (kv.x - mk) * rvk;
        ks[ls][li+1] = (kv.y - mk) * rvk;
        ks[ls][li+2] = (kv.z - mk) * rvk;
        ks[ls][li+3] = (kv.w - mk) * rvk;
        __syncthreads();

        #pragma unroll
        for (int t = 0; t < 4; t++) {
            int ss = g + t * 16;
            float4 kf = *(const float4*)&ks[ss][it * 4];
            float4 qf = *(const float4*)&qs[ss][jt * 4];
            acc[0][0] += kf.x * qf.x; acc[0][1] += kf.x * qf.y;
            acc[0][2] += kf.x * qf.z; acc[0][3] += kf.x * qf.w;
            acc[1][0] += kf.y * qf.x; acc[1][1] += kf.y * qf.y;
            acc[1][2] += kf.y * qf.z; acc[1][3] += kf.y * qf.w;
            acc[2][0] += kf.z * qf.x; acc[2][1] += kf.z * qf.y;
            acc[2][2] += kf.z * qf.z; acc[2][3] += kf.z * qf.w;
            acc[3][0] += kf.w * qf.x; acc[3][1] += kf.w * qf.y;
            acc[3][2] += kf.w * qf.z; acc[3][3] += kf.w * qf.w;
        }
        __syncthreads();
    }

    #pragma unroll
    for (int a = 0; a < 4; a++)
        #pragma unroll
        for (int c = 0; c < 4; c++)
            red[g][it * 4 + a][jt * 4 + c] = acc[a][c];
    __syncthreads();

    const int i2 = tid >> 4, j2 = tid & 15;
    float r = 0.f;
    #pragma unroll
    for (int gg = 0; gg < 16; gg++) r += red[gg][i2][j2];
    part[((size_t)(sl * (B_*HEADS_) + bh)) * 256 + i2 * 16 + j2] = r;
}

// ---------------- reduce slices + temperature + softmax(axis=-2) ----------------
__global__ __launch_bounds__(256) void attn_fin_k(
    const float* __restrict__ part, const float* __restrict__ temp,
    float* __restrict__ attn_out)
{
    const int bh = blockIdx.x;
    __shared__ float sm[16][16];
    const int tid = threadIdx.x;
    const int i2 = tid >> 4, j2 = tid & 15;

    float a = 0.f;
    #pragma unroll
    for (int sl = 0; sl < SLICES; sl++)
        a += part[((size_t)(sl * (B_*HEADS_) + bh)) * 256 + tid];
    a *= temp[j2];
    sm[i2][j2] = a;
    __syncthreads();

    if (tid < 16) {
        int j = tid;
        float mx = -1e30f;
        #pragma unroll
        for (int ii = 0; ii < 16; ii++) mx = fmaxf(mx, sm[ii][j]);
        float e[16]; float ssum = 0.f;
        #pragma unroll
        for (int ii = 0; ii < 16; ii++) { e[ii] = expf(sm[ii][j] - mx); ssum += e[ii]; }
        float inv = 1.f / ssum;
        #pragma unroll
        for (int ii = 0; ii < 16; ii++)
            attn_out[((size_t)bh * 16 + ii) * 16 + j] = e[ii] * inv;
    }
}

// ---------------- WfT[b][e][h*16+d] = sum_j attn[b,h,d,j] * w_out[h*16+j][e] --------
__global__ __launch_bounds__(256) void wfused_k(const float* __restrict__ attn,
                                                const float* __restrict__ w_out,
                                                float* __restrict__ wfT)
{
    const int bh = blockIdx.x;
    const int b = bh >> 4, h = bh & 15;
    const int e = threadIdx.x;
    __shared__ float a[16][16];
    a[threadIdx.x >> 4][threadIdx.x & 15] = attn[(size_t)bh * 256 + threadIdx.x];
    __syncthreads();

    float w[16];
    #pragma unroll
    for (int j = 0; j < 16; j++) w[j] = w_out[(size_t)(h*16 + j) * DIM_ + e];
    #pragma unroll
    for (int d = 0; d < 16; d++) {
        float s = 0.f;
        #pragma unroll
        for (int j = 0; j < 16; j++) s += a[d][j] * w[j];
        wfT[((size_t)b * DIM_ + e) * DIM_ + (h*16 + d)] = s;
    }
}

// ---------------- launch ----------------
extern "C" void kernel_launch(void* const* d_in, const int* in_sizes, int n_in,
                              void* d_out, int out_size)
{
    const float* x      = (const float*)d_in[0];
    const float* w_qkv  = (const float*)d_in[1];
    const float* w_dw   = (const float*)d_in[2];
    const float* w_out  = (const float*)d_in[3];
    const float* temp   = (const float*)d_in[4];
    const float* mean_q = (const float*)d_in[5];
    const float* var_q  = (const float*)d_in[6];
    const float* mean_k = (const float*)d_in[7];
    const float* var_k  = (const float*)d_in[8];
    float* out = (float*)d_out;

    float *qkv, *qkv2, *part, *attn, *wfT, *wqkvT;
    cudaGetSymbolAddress((void**)&qkv,   g_qkv);
    cudaGetSymbolAddress((void**)&qkv2,  g_qkv2);
    cudaGetSymbolAddress((void**)&part,  g_part);
    cudaGetSymbolAddress((void**)&attn,  g_attn);
    cudaGetSymbolAddress((void**)&wfT,   g_wfT);
    cudaGetSymbolAddress((void**)&wqkvT, g_wqkvT);

    cudaFuncSetAttribute(mgemm_k, cudaFuncAttributeMaxDynamicSharedMemorySize, TM_SMEM);

    // 0) transpose w_qkv -> [N][K]
    transp_k<<<(N_QKV * DIM_ + 255) / 256, 256>>>(w_qkv, wqkvT);

    // 1) QKV projection: (131072 x 256) @ (256 x 768) via tf32 mma + cp.async
    mgemm_k<<<dim3(N_QKV / TM_BN, M_TOTAL / TM_BM), 256, TM_SMEM>>>(
        x, DIM_, wqkvT, DIM_, 0, qkv, N_QKV, M_TOTAL, DIM_);

    // 2) depthwise 3x3 conv, SAME (smem-tiled)
    dwconv_k<<<dim3(W_ / 32, H_ / 8, B_ * 48), 256>>>(qkv, w_dw, qkv2);

    // 3) channel attention partials + reduce/softmax
    attn_part_k<<<dim3(B_ * HEADS_, SLICES), 256>>>(qkv2, mean_q, var_q, mean_k, var_k, part);
    attn_fin_k<<<B_ * HEADS_, 256>>>(part, temp, attn);

    // 4) fold attn into output projection
    wfused_k<<<B_ * HEADS_, 256>>>(attn, w_out, wfT);

    // 5) out = v_flat @ WfT[b]^T : (16384 x 256) @ (256 x 256) x 8 batches
    mgemm_k<<<dim3(DIM_ / TM_BN, M_TOTAL / TM_BM), 256, TM_SMEM>>>(
        qkv2 + 2 * DIM_, N_QKV, wfT, DIM_, (long long)DIM_ * DIM_, out, DIM_, HW_, DIM_);
}

// round 5
// speedup vs baseline: 1.0689x; 1.0689x over previous
#include <cuda_runtime.h>
#include <math.h>
#include <stdint.h>

// ---------------- problem constants ----------------
#define B_      8
#define H_      128
#define W_      128
#define DIM_    256
#define HEADS_  16
#define DH_     16
#define HW_     (H_*W_)            // 16384
#define M_TOTAL (B_*HW_)           // 131072
#define N_QKV   (3*DIM_)           // 768
#define SLICES  8

// ---------------- scratch (no allocs -> __device__ globals) ----------------
__device__ float g_xt   [(size_t)M_TOTAL * DIM_];     // tf32-rounded x
__device__ float g_qkv  [(size_t)M_TOTAL * N_QKV];
__device__ float g_qkv2 [(size_t)M_TOTAL * N_QKV];    // v channels tf32-rounded
__device__ float g_part [SLICES * B_ * HEADS_ * DH_ * DH_];
__device__ float g_attn [B_ * HEADS_ * DH_ * DH_];
__device__ float g_wfT  [B_ * DIM_ * DIM_];           // tf32-rounded
__device__ float g_wqkvT[N_QKV * DIM_];               // tf32-rounded

// ---------------- helpers ----------------
__device__ __forceinline__ uint32_t smem_u32(const void* p) {
    uint32_t a;
    asm("{ .reg .u64 t; cvta.to.shared.u64 t, %1; cvt.u32.u64 %0, t; }" : "=r"(a) : "l"(p));
    return a;
}
__device__ __forceinline__ float f2tf32f(float f) {
    uint32_t r; asm("cvt.rna.tf32.f32 %0, %1;" : "=r"(r) : "f"(f));
    return __uint_as_float(r);
}
__device__ __forceinline__ void cp16(uint32_t daddr, const void* g) {
    asm volatile("cp.async.ca.shared.global [%0], [%1], 16;" :: "r"(daddr), "l"(g));
}
#define CP_COMMIT() asm volatile("cp.async.commit_group;" ::: "memory")
#define CP_WAIT(n)  asm volatile("cp.async.wait_group %0;" :: "n"(n) : "memory")

__device__ __forceinline__ void mma_tf32(float* c, const uint32_t* a, const uint32_t* b) {
    asm volatile(
        "mma.sync.aligned.m16n8k8.row.col.f32.tf32.tf32.f32 "
        "{%0,%1,%2,%3}, {%4,%5,%6,%7}, {%8,%9}, {%0,%1,%2,%3};"
        : "+f"(c[0]), "+f"(c[1]), "+f"(c[2]), "+f"(c[3])
        : "r"(a[0]), "r"(a[1]), "r"(a[2]), "r"(a[3]), "r"(b[0]), "r"(b[1]));
}

// ---------------- tf32 mma.sync GEMM, cp.async 2-stage, operands pre-rounded --------
#define TM_BM 128
#define TM_BN 128
#define TM_BK 32
#define TM_PAD 36
#define TM_STAGE (2 * TM_BM * TM_PAD)            // floats per stage (A + B)
#define TM_SMEM  (2 * TM_STAGE * 4)              // 73728 bytes

__global__ __launch_bounds__(256, 2) void mgemm_k(
    const float* __restrict__ A, int lda,
    const float* __restrict__ Bt, int ldb, long long b_stride,
    float* __restrict__ C, int ldc,
    int rows_per_batch, int K)
{
    extern __shared__ float smf[];

    const int tid  = threadIdx.x;
    const int lane = tid & 31;
    const int wid  = tid >> 5;
    const int wm   = wid & 1;
    const int wn   = wid >> 1;
    const int gid  = lane >> 2;
    const int tig  = lane & 3;

    const int m0 = blockIdx.y * TM_BM;
    const int n0 = blockIdx.x * TM_BN;
    const int batch = m0 / rows_per_batch;
    const float* Ap = A  + (size_t)m0 * lda;
    const float* Bp = Bt + (size_t)batch * b_stride + (size_t)n0 * ldb;

    float acc[4][4][4];
    #pragma unroll
    for (int mt = 0; mt < 4; mt++)
        #pragma unroll
        for (int nt = 0; nt < 4; nt++)
            #pragma unroll
            for (int r = 0; r < 4; r++) acc[mt][nt][r] = 0.f;

    const int nk = K / TM_BK;

    #define STAGE_LOAD(S, BUF) do {                                              \
        const float* gA = Ap + (S) * TM_BK;                                       \
        const float* gB = Bp + (S) * TM_BK;                                       \
        float* sa = smf + (BUF) * TM_STAGE;                                       \
        float* sb = sa + TM_BM * TM_PAD;                                          \
        _Pragma("unroll")                                                         \
        for (int i = 0; i < 4; i++) {                                             \
            int idx = i * 256 + tid;                                              \
            int r = idx >> 3, c4 = idx & 7;                                       \
            cp16(smem_u32(sa + r * TM_PAD + c4 * 4), gA + (size_t)r * lda + c4 * 4); \
        }                                                                         \
        _Pragma("unroll")                                                         \
        for (int i = 0; i < 4; i++) {                                             \
            int idx = i * 256 + tid;                                              \
            int r = idx >> 3, c4 = idx & 7;                                       \
            cp16(smem_u32(sb + r * TM_PAD + c4 * 4), gB + (size_t)r * ldb + c4 * 4); \
        }                                                                         \
        CP_COMMIT();                                                              \
    } while (0)

    STAGE_LOAD(0, 0);

    for (int s = 0; s < nk; s++) {
        const int buf = s & 1;
        if (s + 1 < nk) { STAGE_LOAD(s + 1, buf ^ 1); CP_WAIT(1); }
        else            { CP_WAIT(0); }
        __syncthreads();

        const uint32_t* Asf = (const uint32_t*)(smf + buf * TM_STAGE);
        const uint32_t* Bsf = Asf + TM_BM * TM_PAD;

        #pragma unroll
        for (int ks = 0; ks < TM_BK / 8; ks++) {
            const int kc = ks * 8 + tig;
            uint32_t af[4][4], bf[4][2];
            #pragma unroll
            for (int mt = 0; mt < 4; mt++) {
                int row = wm * 64 + mt * 16 + gid;
                af[mt][0] = Asf[row * TM_PAD + kc];
                af[mt][1] = Asf[(row + 8) * TM_PAD + kc];
                af[mt][2] = Asf[row * TM_PAD + kc + 4];
                af[mt][3] = Asf[(row + 8) * TM_PAD + kc + 4];
            }
            #pragma unroll
            for (int nt = 0; nt < 4; nt++) {
                int nrow = wn * 32 + nt * 8 + gid;
                bf[nt][0] = Bsf[nrow * TM_PAD + kc];
                bf[nt][1] = Bsf[nrow * TM_PAD + kc + 4];
            }
            #pragma unroll
            for (int mt = 0; mt < 4; mt++)
                #pragma unroll
                for (int nt = 0; nt < 4; nt++)
                    mma_tf32(acc[mt][nt], af[mt], bf[nt]);
        }
        __syncthreads();
    }

    #pragma unroll
    for (int mt = 0; mt < 4; mt++) {
        #pragma unroll
        for (int nt = 0; nt < 4; nt++) {
            int row = m0 + wm * 64 + mt * 16 + gid;
            int col = n0 + wn * 32 + nt * 8 + tig * 2;
            *(float2*)(C + (size_t)row * ldc + col) =
                make_float2(acc[mt][nt][0], acc[mt][nt][1]);
            *(float2*)(C + (size_t)(row + 8) * ldc + col) =
                make_float2(acc[mt][nt][2], acc[mt][nt][3]);
        }
    }
}

// ---------------- cvt x -> tf32-rounded copy ----------------
__global__ void cvt_x_k(const float* __restrict__ x, float* __restrict__ xt) {
    size_t idx = (size_t)blockIdx.x * blockDim.x + threadIdx.x;
    if (idx >= ((size_t)M_TOTAL * DIM_) / 4) return;
    float4 v = ((const float4*)x)[idx];
    v.x = f2tf32f(v.x); v.y = f2tf32f(v.y);
    v.z = f2tf32f(v.z); v.w = f2tf32f(v.w);
    ((float4*)xt)[idx] = v;
}

// ---------------- transpose + round: w_qkv [K=256, N=768] -> [N][K] ----------------
__global__ void transp_k(const float* __restrict__ w, float* __restrict__ wT) {
    int idx = blockIdx.x * blockDim.x + threadIdx.x;
    if (idx >= N_QKV * DIM_) return;
    int n = idx / DIM_, k = idx % DIM_;
    wT[idx] = f2tf32f(w[(size_t)k * N_QKV + n]);
}

// ---------------- depthwise 3x3 conv, SAME, NHWC, smem-tiled ----------------
// block: 8x32 pixel tile x 16 channels. v channels (cbase>=512) stored tf32-rounded.
__global__ __launch_bounds__(256) void dwconv_k(const float* __restrict__ in,
                                                const float* __restrict__ w,
                                                float* __restrict__ out)
{
    __shared__ float sm[10][34][16];

    const int bx = blockIdx.x;
    const int by = blockIdx.y;
    const int bz = blockIdx.z;
    const int b  = bz / 48, g48 = bz % 48;
    const int cbase = g48 * 16;
    const bool is_v = (cbase >= 2 * DIM_);

    const int tid = threadIdx.x;

    for (int i = tid; i < 10 * 34 * 4; i += 256) {
        int c4 = i & 3;
        int x  = (i >> 2) % 34;
        int y  = (i >> 2) / 34;
        int gy = by * 8 - 1 + y, gx = bx * 32 - 1 + x;
        float4 v = make_float4(0.f, 0.f, 0.f, 0.f);
        if ((unsigned)gy < (unsigned)H_ && (unsigned)gx < (unsigned)W_)
            v = *(const float4*)(in + ((size_t)(b * H_ + gy) * W_ + gx) * N_QKV + cbase + c4 * 4);
        *(float4*)&sm[y][x][c4 * 4] = v;
    }

    const int c4s = tid & 3;
    const int xo  = (tid >> 2) & 31;
    const int yo0 = tid >> 7;
    float4 wv[9];
    #pragma unroll
    for (int t = 0; t < 9; t++)
        wv[t] = *(const float4*)(w + (size_t)t * N_QKV + cbase + c4s * 4);
    __syncthreads();

    #pragma unroll
    for (int i = 0; i < 4; i++) {
        int yo = yo0 + i * 2;
        float4 acc = make_float4(0.f, 0.f, 0.f, 0.f);
        #pragma unroll
        for (int dy = 0; dy < 3; dy++)
            #pragma unroll
            for (int dx = 0; dx < 3; dx++) {
                float4 iv = *(const float4*)&sm[yo + dy][xo + dx][c4s * 4];
                float4 ww = wv[dy * 3 + dx];
                acc.x += iv.x * ww.x; acc.y += iv.y * ww.y;
                acc.z += iv.z * ww.z; acc.w += iv.w * ww.w;
            }
        if (is_v) {
            acc.x = f2tf32f(acc.x); acc.y = f2tf32f(acc.y);
            acc.z = f2tf32f(acc.z); acc.w = f2tf32f(acc.w);
        }
        int gy = by * 8 + yo, gx = bx * 32 + xo;
        *(float4*)(out + ((size_t)(b * H_ + gy) * W_ + gx) * N_QKV + cbase + c4s * 4) = acc;
    }
}

// ---------------- attention partials: 4x4 register tiles ----------------
__global__ __launch_bounds__(256) void attn_part_k(
    const float* __restrict__ qkv2,
    const float* __restrict__ mean_q, const float* __restrict__ var_q,
    const float* __restrict__ mean_k, const float* __restrict__ var_k,
    float* __restrict__ part)
{
    const int bh = blockIdx.x;
    const int sl = blockIdx.y;
    const int b = bh >> 4, h = bh & 15;
    __shared__ float qs[64][16];
    __shared__ float ks[64][16];
    __shared__ float red[16][16][16];

    const int tid  = threadIdx.x;
    const int tile = tid & 15;
    const int g    = tid >> 4;
    const int it   = tile >> 2, jt = tile & 3;
    const int ls   = tid >> 2;
    const int li   = (tid & 3) * 4;
    const float* base = qkv2 + (size_t)b * HW_ * N_QKV + h * DH_;

    float acc[4][4];
    #pragma unroll
    for (int a = 0; a < 4; a++)
        #pragma unroll
        for (int c = 0; c < 4; c++) acc[a][c] = 0.f;

    const int s_beg = sl * (HW_ / SLICES), s_end = s_beg + HW_ / SLICES;

    for (int s0 = s_beg; s0 < s_end; s0 += 64) {
        int s = s0 + ls;
        float mq = mean_q[s], rvq = rsqrtf(var_q[s]);
        float mk = mean_k[s], rvk = rsqrtf(var_k[s]);
        const float* p = base + (size_t)s * N_QKV + li;
        float4 qv = *(const float4*)(p);
        float4 kv = *(const float4*)(p + DIM_);
        qs[ls][li+0] = (qv.x - mq) * rvq;
        qs[ls][li+1] = (qv.y - mq) * rvq;
        qs[ls][li+2] = (qv.z - mq) * rvq;
        qs[ls][li+3] = (qv.w - mq) * rvq;
        ks[ls][li+0] = (kv.x - mk) * rvk;
        ks[ls][li+1] = (kv.y - mk) * rvk;
        ks[ls][li+2] = (kv.z - mk) * rvk;
        ks[ls][li+3] = (kv.w - mk) * rvk;
        __syncthreads();

        #pragma unroll
        for (int t = 0; t < 4; t++) {
            int ss = g + t * 16;
            float4 kf = *(const float4*)&ks[ss][it * 4];
            float4 qf = *(const float4*)&qs[ss][jt * 4];
            acc[0][0] += kf.x * qf.x; acc[0][1] += kf.x * qf.y;
            acc[0][2] += kf.x * qf.z; acc[0][3] += kf.x * qf.w;
            acc[1][0] += kf.y * qf.x; acc[1][1] += kf.y * qf.y;
            acc[1][2] += kf.y * qf.z; acc[1][3] += kf.y * qf.w;
            acc[2][0] += kf.z * qf.x; acc[2][1] += kf.z * qf.y;
            acc[2][2] += kf.z * qf.z; acc[2][3] += kf.z * qf.w;
            acc[3][0] += kf.w * qf.x; acc[3][1] += kf.w * qf.y;
            acc[3][2] += kf.w * qf.z; acc[3][3] += kf.w * qf.w;
        }
        __syncthreads();
    }

    #pragma unroll
    for (int a = 0; a < 4; a++)
        #pragma unroll
        for (int c = 0; c < 4; c++)
            red[g][it * 4 + a][jt * 4 + c] = acc[a][c];
    __syncthreads();

    const int i2 = tid >> 4, j2 = tid & 15;
    float r = 0.f;
    #pragma unroll
    for (int gg = 0; gg < 16; gg++) r += red[gg][i2][j2];
    part[((size_t)(sl * (B_*HEADS_) + bh)) * 256 + i2 * 16 + j2] = r;
}

// ---------------- reduce slices + temperature + softmax(axis=-2) ----------------
__global__ __launch_bounds__(256) void attn_fin_k(
    const float* __restrict__ part, const float* __restrict__ temp,
    float* __restrict__ attn_out)
{
    const int bh = blockIdx.x;
    __shared__ float sm[16][16];
    const int tid = threadIdx.x;
    const int i2 = tid >> 4, j2 = tid & 15;

    float a = 0.f;
    #pragma unroll
    for (int sl = 0; sl < SLICES; sl++)
        a += part[((size_t)(sl * (B_*HEADS_) + bh)) * 256 + tid];
    a *= temp[j2];
    sm[i2][j2] = a;
    __syncthreads();

    if (tid < 16) {
        int j = tid;
        float mx = -1e30f;
        #pragma unroll
        for (int ii = 0; ii < 16; ii++) mx = fmaxf(mx, sm[ii][j]);
        float e[16]; float ssum = 0.f;
        #pragma unroll
        for (int ii = 0; ii < 16; ii++) { e[ii] = expf(sm[ii][j] - mx); ssum += e[ii]; }
        float inv = 1.f / ssum;
        #pragma unroll
        for (int ii = 0; ii < 16; ii++)
            attn_out[((size_t)bh * 16 + ii) * 16 + j] = e[ii] * inv;
    }
}

// ---------------- WfT (tf32-rounded) ----------------
__global__ __launch_bounds__(256) void wfused_k(const float* __restrict__ attn,
                                                const float* __restrict__ w_out,
                                                float* __restrict__ wfT)
{
    const int bh = blockIdx.x;
    const int b = bh >> 4, h = bh & 15;
    const int e = threadIdx.x;
    __shared__ float a[16][16];
    a[threadIdx.x >> 4][threadIdx.x & 15] = attn[(size_t)bh * 256 + threadIdx.x];
    __syncthreads();

    float w[16];
    #pragma unroll
    for (int j = 0; j < 16; j++) w[j] = w_out[(size_t)(h*16 + j) * DIM_ + e];
    #pragma unroll
    for (int d = 0; d < 16; d++) {
        float s = 0.f;
        #pragma unroll
        for (int j = 0; j < 16; j++) s += a[d][j] * w[j];
        wfT[((size_t)b * DIM_ + e) * DIM_ + (h*16 + d)] = f2tf32f(s);
    }
}

// ---------------- launch ----------------
extern "C" void kernel_launch(void* const* d_in, const int* in_sizes, int n_in,
                              void* d_out, int out_size)
{
    const float* x      = (const float*)d_in[0];
    const float* w_qkv  = (const float*)d_in[1];
    const float* w_dw   = (const float*)d_in[2];
    const float* w_out  = (const float*)d_in[3];
    const float* temp   = (const float*)d_in[4];
    const float* mean_q = (const float*)d_in[5];
    const float* var_q  = (const float*)d_in[6];
    const float* mean_k = (const float*)d_in[7];
    const float* var_k  = (const float*)d_in[8];
    float* out = (float*)d_out;

    float *xt, *qkv, *qkv2, *part, *attn, *wfT, *wqkvT;
    cudaGetSymbolAddress((void**)&xt,    g_xt);
    cudaGetSymbolAddress((void**)&qkv,   g_qkv);
    cudaGetSymbolAddress((void**)&qkv2,  g_qkv2);
    cudaGetSymbolAddress((void**)&part,  g_part);
    cudaGetSymbolAddress((void**)&attn,  g_attn);
    cudaGetSymbolAddress((void**)&wfT,   g_wfT);
    cudaGetSymbolAddress((void**)&wqkvT, g_wqkvT);

    cudaFuncSetAttribute(mgemm_k, cudaFuncAttributeMaxDynamicSharedMemorySize, TM_SMEM);

    // 0) pre-round operands to tf32
    cvt_x_k<<<(M_TOTAL * DIM_ / 4 + 255) / 256, 256>>>(x, xt);
    transp_k<<<(N_QKV * DIM_ + 255) / 256, 256>>>(w_qkv, wqkvT);

    // 1) QKV projection (pre-rounded operands, no inner cvt)
    mgemm_k<<<dim3(N_QKV / TM_BN, M_TOTAL / TM_BM), 256, TM_SMEM>>>(
        xt, DIM_, wqkvT, DIM_, 0, qkv, N_QKV, M_TOTAL, DIM_);

    // 2) depthwise 3x3 conv (v channels stored tf32-rounded)
    dwconv_k<<<dim3(W_ / 32, H_ / 8, B_ * 48), 256>>>(qkv, w_dw, qkv2);

    // 3) channel attention partials + reduce/softmax
    attn_part_k<<<dim3(B_ * HEADS_, SLICES), 256>>>(qkv2, mean_q, var_q, mean_k, var_k, part);
    attn_fin_k<<<B_ * HEADS_, 256>>>(part, temp, attn);

    // 4) fold attn into output projection (tf32-rounded)
    wfused_k<<<B_ * HEADS_, 256>>>(attn, w_out, wfT);

    // 5) out = v_flat @ WfT[b]^T
    mgemm_k<<<dim3(DIM_ / TM_BN, M_TOTAL / TM_BM), 256, TM_SMEM>>>(
        qkv2 + 2 * DIM_, N_QKV, wfT, DIM_, (long long)DIM_ * DIM_, out, DIM_, HW_, DIM_);
}